// round 5
// baseline (speedup 1.0000x reference)
#include <cuda_runtime.h>

// 4-level 2D Haar DWT, fully fused. Tile = 128x64 input per 256-thread block,
// 8 quads/thread at level 0 with all 8 LDG.128 issued before compute (MLP=8).
// No cache hints (measured regression with .CS on R3).
// Grid: (8, 4, 192) = 6144 blocks.
//
// Output: concat of levels l=0..3, each (192, 4, S, S), S = 256 >> l
//   subband order: 0=cA, 1=cH, 2=cV, 3=cD

#define NIMG 192
#define HW   512

#define OFF0 0ull
#define OFF1 (OFF0 + (unsigned long long)NIMG * 4ull * 256ull * 256ull)
#define OFF2 (OFF1 + (unsigned long long)NIMG * 4ull * 128ull * 128ull)
#define OFF3 (OFF2 + (unsigned long long)NIMG * 4ull *  64ull *  64ull)

#define HAAR(a, b, c, d, cA, cH, cV, cD)                    \
    do {                                                    \
        float _hs0 = (a) + (b), _hd0 = (a) - (b);           \
        float _hs1 = (c) + (d), _hd1 = (c) - (d);           \
        (cA) = (_hs0 + _hs1) * 0.5f;                        \
        (cH) = (_hs0 - _hs1) * 0.5f;                        \
        (cV) = (_hd0 + _hd1) * 0.5f;                        \
        (cD) = (_hd0 - _hd1) * 0.5f;                        \
    } while (0)

// 4 adjacent quads from two row-pair float4s -> 4 subband float4s
#define HAAR4(r0a, r0b, r1a, r1b, cA4, cH4, cV4, cD4)                        \
    do {                                                                     \
        HAAR((r0a).x, (r0a).y, (r1a).x, (r1a).y, (cA4).x, (cH4).x, (cV4).x, (cD4).x); \
        HAAR((r0a).z, (r0a).w, (r1a).z, (r1a).w, (cA4).y, (cH4).y, (cV4).y, (cD4).y); \
        HAAR((r0b).x, (r0b).y, (r1b).x, (r1b).y, (cA4).z, (cH4).z, (cV4).z, (cD4).z); \
        HAAR((r0b).z, (r0b).w, (r1b).z, (r1b).w, (cA4).w, (cH4).w, (cV4).w, (cD4).w); \
    } while (0)

__global__ __launch_bounds__(256) void fwt_kernel(const float* __restrict__ x,
                                                  float* __restrict__ out) {
    const int img = blockIdx.z;
    const int ty  = blockIdx.y;   // 0..3  (128-row slabs)
    const int tx  = blockIdx.x;   // 0..7  (64-col slabs)
    const int tid = threadIdx.x;

    __shared__ float sB[64][33];  // level-0 cA (64x32)
    __shared__ float sC[32][17];  // level-1 cA (32x16)
    __shared__ float sD[16][9];   // level-2 cA (16x8)

    // ---- level 0: 128x64 input -> 64x32 quads, S=256 ----
    {
        const int qi  = tid >> 3;   // 0..31 (quad row within group)
        const int qjg = tid & 7;    // 4-quad col group -> input cols qjg*8..+7

        const float* src0 = x + ((size_t)img * HW + (size_t)ty * 128 + 2 * qi) * HW
                              + (size_t)tx * 64 + qjg * 8;
        const float* src1 = src0 + 64 * HW;   // quad row qi+32

        // all 8 loads issued before any compute
        const float4 ra0 = *reinterpret_cast<const float4*>(src0);
        const float4 rb0 = *reinterpret_cast<const float4*>(src0 + 4);
        const float4 rc0 = *reinterpret_cast<const float4*>(src0 + HW);
        const float4 rd0 = *reinterpret_cast<const float4*>(src0 + HW + 4);
        const float4 ra1 = *reinterpret_cast<const float4*>(src1);
        const float4 rb1 = *reinterpret_cast<const float4*>(src1 + 4);
        const float4 rc1 = *reinterpret_cast<const float4*>(src1 + HW);
        const float4 rd1 = *reinterpret_cast<const float4*>(src1 + HW + 4);

        const int S = 256;
        float* base = out + OFF0 + (size_t)img * 4ull * S * S;
        const int gj = tx * 32 + qjg * 4;

        // group 0 (quad row qi)
        {
            float4 cA4, cH4, cV4, cD4;
            HAAR4(ra0, rb0, rc0, rd0, cA4, cH4, cV4, cD4);
            const int gi = ty * 64 + qi;
            const size_t o = (size_t)gi * S + gj;
            *reinterpret_cast<float4*>(base + o)                 = cA4;
            *reinterpret_cast<float4*>(base + (size_t)S * S + o) = cH4;
            *reinterpret_cast<float4*>(base + 2ull * S * S + o)  = cV4;
            *reinterpret_cast<float4*>(base + 3ull * S * S + o)  = cD4;
            sB[qi][qjg * 4 + 0] = cA4.x;
            sB[qi][qjg * 4 + 1] = cA4.y;
            sB[qi][qjg * 4 + 2] = cA4.z;
            sB[qi][qjg * 4 + 3] = cA4.w;
        }
        // group 1 (quad row qi+32)
        {
            float4 cA4, cH4, cV4, cD4;
            HAAR4(ra1, rb1, rc1, rd1, cA4, cH4, cV4, cD4);
            const int gi = ty * 64 + qi + 32;
            const size_t o = (size_t)gi * S + gj;
            *reinterpret_cast<float4*>(base + o)                 = cA4;
            *reinterpret_cast<float4*>(base + (size_t)S * S + o) = cH4;
            *reinterpret_cast<float4*>(base + 2ull * S * S + o)  = cV4;
            *reinterpret_cast<float4*>(base + 3ull * S * S + o)  = cD4;
            sB[qi + 32][qjg * 4 + 0] = cA4.x;
            sB[qi + 32][qjg * 4 + 1] = cA4.y;
            sB[qi + 32][qjg * 4 + 2] = cA4.z;
            sB[qi + 32][qjg * 4 + 3] = cA4.w;
        }
    }
    __syncthreads();

    // ---- level 1: 64x32 -> 32x16 quads, S=128 (128 threads x 4 quads) ----
    if (tid < 128) {
        const int qi  = tid >> 2;   // 0..31
        const int qjg = tid & 3;    // cols qjg*8..+7 of sB

        float4 cA4, cH4, cV4, cD4;
        {
            const int r0 = 2 * qi, r1 = 2 * qi + 1, c0 = qjg * 8;
            HAAR(sB[r0][c0 + 0], sB[r0][c0 + 1], sB[r1][c0 + 0], sB[r1][c0 + 1],
                 cA4.x, cH4.x, cV4.x, cD4.x);
            HAAR(sB[r0][c0 + 2], sB[r0][c0 + 3], sB[r1][c0 + 2], sB[r1][c0 + 3],
                 cA4.y, cH4.y, cV4.y, cD4.y);
            HAAR(sB[r0][c0 + 4], sB[r0][c0 + 5], sB[r1][c0 + 4], sB[r1][c0 + 5],
                 cA4.z, cH4.z, cV4.z, cD4.z);
            HAAR(sB[r0][c0 + 6], sB[r0][c0 + 7], sB[r1][c0 + 6], sB[r1][c0 + 7],
                 cA4.w, cH4.w, cV4.w, cD4.w);
        }

        const int S = 128;
        float* base = out + OFF1 + (size_t)img * 4ull * S * S;
        const int gi = ty * 32 + qi, gj = tx * 16 + qjg * 4;
        const size_t o = (size_t)gi * S + gj;
        *reinterpret_cast<float4*>(base + o)                 = cA4;
        *reinterpret_cast<float4*>(base + (size_t)S * S + o) = cH4;
        *reinterpret_cast<float4*>(base + 2ull * S * S + o)  = cV4;
        *reinterpret_cast<float4*>(base + 3ull * S * S + o)  = cD4;

        sC[qi][qjg * 4 + 0] = cA4.x;
        sC[qi][qjg * 4 + 1] = cA4.y;
        sC[qi][qjg * 4 + 2] = cA4.z;
        sC[qi][qjg * 4 + 3] = cA4.w;
    }
    __syncthreads();

    // ---- level 2: 32x16 -> 16x8 quads, S=64 (32 threads x 4 quads) ----
    if (tid < 32) {
        const int qi  = tid >> 1;   // 0..15
        const int qjg = tid & 1;    // cols qjg*8..+7 of sC

        float4 cA4, cH4, cV4, cD4;
        {
            const int r0 = 2 * qi, r1 = 2 * qi + 1, c0 = qjg * 8;
            HAAR(sC[r0][c0 + 0], sC[r0][c0 + 1], sC[r1][c0 + 0], sC[r1][c0 + 1],
                 cA4.x, cH4.x, cV4.x, cD4.x);
            HAAR(sC[r0][c0 + 2], sC[r0][c0 + 3], sC[r1][c0 + 2], sC[r1][c0 + 3],
                 cA4.y, cH4.y, cV4.y, cD4.y);
            HAAR(sC[r0][c0 + 4], sC[r0][c0 + 5], sC[r1][c0 + 4], sC[r1][c0 + 5],
                 cA4.z, cH4.z, cV4.z, cD4.z);
            HAAR(sC[r0][c0 + 6], sC[r0][c0 + 7], sC[r1][c0 + 6], sC[r1][c0 + 7],
                 cA4.w, cH4.w, cV4.w, cD4.w);
        }

        const int S = 64;
        float* base = out + OFF2 + (size_t)img * 4ull * S * S;
        const int gi = ty * 16 + qi, gj = tx * 8 + qjg * 4;
        const size_t o = (size_t)gi * S + gj;
        *reinterpret_cast<float4*>(base + o)                 = cA4;
        *reinterpret_cast<float4*>(base + (size_t)S * S + o) = cH4;
        *reinterpret_cast<float4*>(base + 2ull * S * S + o)  = cV4;
        *reinterpret_cast<float4*>(base + 3ull * S * S + o)  = cD4;

        sD[qi][qjg * 4 + 0] = cA4.x;
        sD[qi][qjg * 4 + 1] = cA4.y;
        sD[qi][qjg * 4 + 2] = cA4.z;
        sD[qi][qjg * 4 + 3] = cA4.w;
    }
    __syncthreads();

    // ---- level 3: 16x8 -> 8x4 quads, S=32 (8 threads x 4 quads) ----
    if (tid < 8) {
        const int qi = tid;  // 0..7, full 4-quad row

        float4 cA4, cH4, cV4, cD4;
        {
            const int r0 = 2 * qi, r1 = 2 * qi + 1;
            HAAR(sD[r0][0], sD[r0][1], sD[r1][0], sD[r1][1], cA4.x, cH4.x, cV4.x, cD4.x);
            HAAR(sD[r0][2], sD[r0][3], sD[r1][2], sD[r1][3], cA4.y, cH4.y, cV4.y, cD4.y);
            HAAR(sD[r0][4], sD[r0][5], sD[r1][4], sD[r1][5], cA4.z, cH4.z, cV4.z, cD4.z);
            HAAR(sD[r0][6], sD[r0][7], sD[r1][6], sD[r1][7], cA4.w, cH4.w, cV4.w, cD4.w);
        }

        const int S = 32;
        float* base = out + OFF3 + (size_t)img * 4ull * S * S;
        const int gi = ty * 8 + qi, gj = tx * 4;
        const size_t o = (size_t)gi * S + gj;
        *reinterpret_cast<float4*>(base + o)                 = cA4;
        *reinterpret_cast<float4*>(base + (size_t)S * S + o) = cH4;
        *reinterpret_cast<float4*>(base + 2ull * S * S + o)  = cV4;
        *reinterpret_cast<float4*>(base + 3ull * S * S + o)  = cD4;
    }
}

extern "C" void kernel_launch(void* const* d_in, const int* in_sizes, int n_in,
                              void* d_out, int out_size) {
    const float* x = (const float*)d_in[0];
    float* out     = (float*)d_out;
    dim3 grid(8, 4, NIMG);
    fwt_kernel<<<grid, 256>>>(x, out);
}